// round 16
// baseline (speedup 1.0000x reference)
#include <cuda_runtime.h>
#include <cuda_bf16.h>
#include <cuda_fp8.h>
#include <cstdint>

#define M_TOK   16384
#define L_SEQ   4096
#define D_MODEL 1024
#define DI      2048
#define DS      16
#define DH      1024
#define YK8     1088          // fp8 concat K: 16 a1 + 48 pad + 1024 b_h

// scale factors (power-of-2)
#define S_XN  4.0f
#define S_W   128.0f
#define S_CB  64.0f
#define S_YC  64.0f
#define S_F   256.0f

// ---------------- bf16 GEMM tiling (Wb precompute only) ----------------
#define BM 128
#define BN 128
#define PITCH 40
#define STAGE_BYTES (128 * PITCH * 2)            // 10240
#define NSTAGE 4
#define SMEM_TOTAL (NSTAGE * 2 * STAGE_BYTES)    // 81920

// ---------------- fp8 GEMM (A smem-staged, B direct-LDG) ----------------
#define QPITCH 80                                 // bytes per smem row (A tile)
#define QSTAGE_A (128 * QPITCH)                   // 10240
#define QSMEM2 (NSTAGE * QSTAGE_A)                // 40960

// ---------------- scratch (device globals) ----------------
__device__ __align__(16) uint8_t g_xn8 [(size_t)M_TOK * D_MODEL];
__device__ __nv_bfloat16 g_gate[(size_t)M_TOK * DI];
__device__ __nv_bfloat16 g_val [(size_t)M_TOK * DI];
__device__ __nv_bfloat16 g_ca  [(size_t)M_TOK * DI];
__device__ __align__(16) uint8_t g_cb8 [(size_t)M_TOK * DI];
__device__ __align__(16) uint8_t g_yc8 [(size_t)M_TOK * YK8];
__device__ __align__(16) uint8_t g_f8  [(size_t)M_TOK * DI];

// plain fp8 weights (N,K) then fragment-shuffled copies (suffix q)
__device__ __align__(16) uint8_t g_inw8 [(size_t)2 * DI * D_MODEL];
__device__ __align__(16) uint8_t g_inwq [(size_t)2 * DI * D_MODEL];
__device__ __align__(16) uint8_t g_outw8[(size_t)D_MODEL * DI];
__device__ __align__(16) uint8_t g_outwq[(size_t)D_MODEL * DI];
__device__ __align__(16) uint8_t g_Wb8  [(size_t)DH * DI];
__device__ __align__(16) uint8_t g_Wbq  [(size_t)DH * DI];
__device__ __align__(16) uint8_t g_wf8  [(size_t)DI * YK8];
__device__ __align__(16) uint8_t g_wfq  [(size_t)DI * YK8];
__device__ __nv_bfloat16 g_hbw  [(size_t)DH * DI];
__device__ __nv_bfloat16 g_pwT  [(size_t)DI * DI];
__device__ __nv_bfloat16 g_Wb   [(size_t)DH * DI];
__device__ float         g_T    [DS * DH];
__device__ float         g_biasb[DH];
__device__ float         g_biasy[DI];

// ---------------- PTX helpers ----------------
__device__ __forceinline__ uint32_t smem_u32(const void* p) {
    uint32_t a;
    asm("{ .reg .u64 t; cvta.to.shared.u64 t, %1; cvt.u32.u64 %0, t; }" : "=r"(a) : "l"(p));
    return a;
}
__device__ __forceinline__ void cpasync16(uint32_t dst, const void* src) {
    asm volatile("cp.async.cg.shared.global [%0], [%1], 16;" :: "r"(dst), "l"(src));
}
#define CP_COMMIT() asm volatile("cp.async.commit_group;" ::: "memory")
#define CP_WAIT2()  asm volatile("cp.async.wait_group 2;" ::: "memory")
#define CP_WAIT0()  asm volatile("cp.async.wait_group 0;" ::: "memory")

__device__ __forceinline__ void ldsm4(uint32_t* r, uint32_t addr) {
    asm volatile("ldmatrix.sync.aligned.m8n8.x4.shared.b16 {%0,%1,%2,%3}, [%4];"
        : "=r"(r[0]), "=r"(r[1]), "=r"(r[2]), "=r"(r[3]) : "r"(addr));
}
__device__ __forceinline__ void ldsm2(uint32_t* r, uint32_t addr) {
    asm volatile("ldmatrix.sync.aligned.m8n8.x2.shared.b16 {%0,%1}, [%2];"
        : "=r"(r[0]), "=r"(r[1]) : "r"(addr));
}
__device__ __forceinline__ void mma16816(float* d, const uint32_t* a, const uint32_t* b) {
    asm volatile("mma.sync.aligned.m16n8k16.row.col.f32.bf16.bf16.f32 "
        "{%0,%1,%2,%3}, {%4,%5,%6,%7}, {%8,%9}, {%0,%1,%2,%3};"
        : "+f"(d[0]), "+f"(d[1]), "+f"(d[2]), "+f"(d[3])
        : "r"(a[0]), "r"(a[1]), "r"(a[2]), "r"(a[3]), "r"(b[0]), "r"(b[1]));
}
__device__ __forceinline__ void qmma16832(float* d, const uint32_t* a, const uint32_t* b) {
    asm volatile("mma.sync.aligned.m16n8k32.row.col.f32.e4m3.e4m3.f32 "
        "{%0,%1,%2,%3}, {%4,%5,%6,%7}, {%8,%9}, {%0,%1,%2,%3};"
        : "+f"(d[0]), "+f"(d[1]), "+f"(d[2]), "+f"(d[3])
        : "r"(a[0]), "r"(a[1]), "r"(a[2]), "r"(a[3]), "r"(b[0]), "r"(b[1]));
}

__device__ __forceinline__ uint8_t f2fp8(float v) {
    return (uint8_t)__nv_cvt_float_to_fp8(v, __NV_SATFINITE, __NV_E4M3);
}
__device__ __forceinline__ uint16_t f2fp8x2(float a, float b) {
    return (uint16_t)__nv_cvt_float2_to_fp8x2(make_float2(a, b), __NV_SATFINITE, __NV_E4M3);
}

// ================= bf16 GEMM (Wb precompute only) =================
__global__ void __launch_bounds__(256, 2) mma_gemm_k(
    const __nv_bfloat16* __restrict__ X, const __nv_bfloat16* __restrict__ W,
    __nv_bfloat16* __restrict__ outp, int out_stride, int K)
{
    extern __shared__ char smem[];
    uint32_t sA = smem_u32(smem);
    uint32_t sB = sA + NSTAGE * STAGE_BYTES;
    int tid = threadIdx.x, warp = tid >> 5, lane = tid & 31;
    int wm = warp >> 2, wn = warp & 3;
    int bm = blockIdx.y * BM, bn = blockIdx.x * BN;
    int NC = K / 32;

    float acc[4][4][4];
    #pragma unroll
    for (int mi = 0; mi < 4; mi++)
        #pragma unroll
        for (int ni = 0; ni < 4; ni++)
            #pragma unroll
            for (int e = 0; e < 4; e++) acc[mi][ni][e] = 0.f;

    auto stage_load = [&](int st, int c) {
        uint32_t a = sA + st * STAGE_BYTES;
        uint32_t b = sB + st * STAGE_BYTES;
        int k0 = c * 32;
        #pragma unroll
        for (int it = 0; it < 2; it++) {
            int id = tid + it * 256;
            int r = id >> 2, s = id & 3;
            uint32_t off = (uint32_t)(r * PITCH + s * 8) * 2;
            cpasync16(a + off, X + (size_t)(bm + r) * K + k0 + s * 8);
            cpasync16(b + off, W + (size_t)(bn + r) * K + k0 + s * 8);
        }
    };

    #pragma unroll
    for (int c = 0; c < NSTAGE - 1; c++) { stage_load(c, c); CP_COMMIT(); }

    for (int c = 0; c < NC; c++) {
        int st = c & (NSTAGE - 1);
        CP_WAIT2();
        __syncthreads();
        if (c + NSTAGE - 1 < NC) stage_load((c + NSTAGE - 1) & (NSTAGE - 1), c + NSTAGE - 1);
        CP_COMMIT();

        uint32_t aBase = sA + st * STAGE_BYTES;
        uint32_t bBase = sB + st * STAGE_BYTES;
        #pragma unroll
        for (int kk = 0; kk < 2; kk++) {
            uint32_t af[4][4], bf[4][2];
            #pragma unroll
            for (int mi = 0; mi < 4; mi++) {
                int row = wm * 64 + mi * 16 + (lane & 15);
                ldsm4(af[mi], aBase + (uint32_t)(row * PITCH + kk * 16 + (lane >> 4) * 8) * 2);
            }
            #pragma unroll
            for (int ni = 0; ni < 4; ni++) {
                int row = wn * 32 + ni * 8 + (lane & 7);
                ldsm2(bf[ni], bBase + (uint32_t)(row * PITCH + kk * 16 + ((lane >> 3) & 1) * 8) * 2);
            }
            #pragma unroll
            for (int mi = 0; mi < 4; mi++)
                #pragma unroll
                for (int ni = 0; ni < 4; ni++)
                    mma16816(acc[mi][ni], af[mi], bf[ni]);
        }
    }
    CP_WAIT0();

    #pragma unroll
    for (int mi = 0; mi < 4; mi++)
        #pragma unroll
        for (int ni = 0; ni < 4; ni++) {
            int gn = bn + wn * 32 + ni * 8 + (lane & 3) * 2;
            #pragma unroll
            for (int h = 0; h < 2; h++) {
                int gm = bm + wm * 64 + mi * 16 + (lane >> 2) + h * 8;
                *(__nv_bfloat162*)(outp + (size_t)gm * out_stride + gn) =
                    __floats2bfloat162_rn(acc[mi][ni][h * 2], acc[mi][ni][h * 2 + 1]);
            }
        }
}

// ================= fp8 GEMM v2: A via smem, B via direct LDG =================
enum { QEPI_INPROJ = 0, QEPI_FP8 = 1, QEPI_GATE = 2, QEPI_RESID = 3 };

// C[m,n] = inv_s * sum_k X[m,k]*W[n,k] + bias[n]
// Wq: fragment-linear layout ((kt*NT+nt)*2+r)*128 + lane*4
template<int EPI>
__global__ void __launch_bounds__(256, 2) qgemm2_k(
    const uint8_t* __restrict__ X, const uint8_t* __restrict__ Wq,
    const float* __restrict__ bias, void* __restrict__ outp, void* __restrict__ outp2,
    int ostride,
    const __nv_bfloat16* __restrict__ gate, const float* __restrict__ resid,
    int Kb, int NT, float inv_s, float s_out)
{
    extern __shared__ char smem[];
    uint32_t sA = smem_u32(smem);
    int tid = threadIdx.x, warp = tid >> 5, lane = tid & 31;
    int wm = warp >> 2, wn = warp & 3;           // 2x4 warp grid, warp tile 64x32
    int bm = blockIdx.y * BM, bn = blockIdx.x * BN;
    int NC = Kb / 64;

    float acc[4][4][4];
    #pragma unroll
    for (int mi = 0; mi < 4; mi++)
        #pragma unroll
        for (int ni = 0; ni < 4; ni++)
            #pragma unroll
            for (int e = 0; e < 4; e++) acc[mi][ni][e] = 0.f;

    auto stage_load = [&](int st, int c) {
        uint32_t a = sA + st * QSTAGE_A;
        int k0 = c * 64;
        #pragma unroll
        for (int it = 0; it < 2; it++) {
            int id = tid + it * 256;
            int r = id >> 2, s = id & 3;
            cpasync16(a + (uint32_t)(r * QPITCH + s * 16),
                      X + (size_t)(bm + r) * Kb + k0 + s * 16);
        }
    };

    #pragma unroll
    for (int c = 0; c < NSTAGE - 1; c++) { stage_load(c, c); CP_COMMIT(); }

    // B fragment base: warp's first n8 tile, plus per-lane 4B offset
    const uint8_t* bbase = Wq + ((size_t)((bn >> 3) + wn * 4)) * 256 + (uint32_t)lane * 4;
    size_t chunkStride = (size_t)NT * 512;     // 2 kt per 64B chunk
    uint32_t o1 = (uint32_t)NT * 256;          // kt (kk) stride

    uint32_t b0[16], b1[16];
    auto ldgB = [&](uint32_t* b, int c) {
        const uint8_t* p = bbase + (size_t)c * chunkStride;
        #pragma unroll
        for (int kk = 0; kk < 2; kk++)
            #pragma unroll
            for (int ni = 0; ni < 4; ni++)
                #pragma unroll
                for (int r = 0; r < 2; r++)
                    b[kk * 8 + ni * 2 + r] =
                        __ldg((const uint32_t*)(p + (size_t)kk * o1 + ni * 256 + r * 128));
    };
    ldgB(b0, 0);

    auto compute = [&](int c, const uint32_t* b) {
        int st = c & (NSTAGE - 1);
        CP_WAIT2();
        __syncthreads();
        if (c + NSTAGE - 1 < NC) stage_load((c + NSTAGE - 1) & (NSTAGE - 1), c + NSTAGE - 1);
        CP_COMMIT();
        uint32_t aBase = sA + st * QSTAGE_A;
        #pragma unroll
        for (int kk = 0; kk < 2; kk++) {
            uint32_t af[4][4];
            #pragma unroll
            for (int mi = 0; mi < 4; mi++) {
                int row = wm * 64 + mi * 16 + (lane & 15);
                ldsm4(af[mi], aBase + (uint32_t)(row * QPITCH + kk * 32 + (lane >> 4) * 16));
            }
            #pragma unroll
            for (int mi = 0; mi < 4; mi++)
                #pragma unroll
                for (int ni = 0; ni < 4; ni++)
                    qmma16832(acc[mi][ni], af[mi], &b[kk * 8 + ni * 2]);
        }
    };

    int cc = 0;
    for (; cc + 1 < NC; cc += 2) {
        ldgB(b1, cc + 1);
        compute(cc, b0);
        if (cc + 2 < NC) ldgB(b0, cc + 2);
        compute(cc + 1, b1);
    }
    if (cc < NC) compute(cc, b0);
    CP_WAIT0();

    // -------- epilogue --------
    #pragma unroll
    for (int mi = 0; mi < 4; mi++) {
        #pragma unroll
        for (int ni = 0; ni < 4; ni++) {
            int gn = bn + wn * 32 + ni * 8 + (lane & 3) * 2;
            float bv0 = 0.f, bv1 = 0.f;
            if (bias) { bv0 = bias[gn]; bv1 = bias[gn + 1]; }
            #pragma unroll
            for (int h = 0; h < 2; h++) {
                int gm = bm + wm * 64 + mi * 16 + (lane >> 2) + h * 8;
                float v0 = acc[mi][ni][h * 2 + 0] * inv_s + bv0;
                float v1 = acc[mi][ni][h * 2 + 1] * inv_s + bv1;
                if (EPI == QEPI_INPROJ) {
                    if (gn < DI) {
                        v0 = 1.f / (1.f + __expf(-v0));
                        v1 = 1.f / (1.f + __expf(-v1));
                        *(__nv_bfloat162*)((__nv_bfloat16*)outp + (size_t)gm * DI + gn) =
                            __floats2bfloat162_rn(v0, v1);
                    } else {
                        *(__nv_bfloat162*)((__nv_bfloat16*)outp2 + (size_t)gm * DI + gn - DI) =
                            __floats2bfloat162_rn(v0, v1);
                    }
                } else if (EPI == QEPI_FP8) {
                    uint8_t* op = (uint8_t*)outp + (size_t)gm * ostride + gn;
                    *(uint16_t*)op = f2fp8x2(v0 * s_out, v1 * s_out);
                } else if (EPI == QEPI_GATE) {
                    __nv_bfloat162 g2 = *(const __nv_bfloat162*)(gate + (size_t)gm * DI + gn);
                    v0 *= __bfloat162float(g2.x);
                    v1 *= __bfloat162float(g2.y);
                    uint8_t* op = (uint8_t*)outp + (size_t)gm * ostride + gn;
                    *(uint16_t*)op = f2fp8x2(v0 * s_out, v1 * s_out);
                } else {  // QEPI_RESID
                    const float* rp = resid + (size_t)gm * ostride + gn;
                    float* op = (float*)outp + (size_t)gm * ostride + gn;
                    float2 r2 = *(const float2*)rp;
                    float2 o2; o2.x = v0 + r2.x; o2.y = v1 + r2.y;
                    *(float2*)op = o2;
                }
            }
        }
    }
}

// ---------------- weight fragment shuffle: plain fp8 (N,K) -> fragment-linear ----------------
__global__ void shuffleB_k(const uint8_t* __restrict__ src, uint8_t* __restrict__ dst,
                           int N, int K) {
    int idx = blockIdx.x * 256 + threadIdx.x;       // one per 4 bytes
    int total = (N * K) >> 2;
    if (idx >= total) return;
    int lane = idx & 31;
    int r = (idx >> 5) & 1;
    int t = idx >> 6;
    int NT = N >> 3;
    int kt = t / NT, nt = t - kt * NT;
    int n = nt * 8 + (lane >> 2);
    int k = kt * 32 + r * 16 + (lane & 3) * 4;
    *(uint32_t*)(dst + (size_t)idx * 4) = *(const uint32_t*)(src + (size_t)n * K + k);
}

// ---------------- small kernels ----------------
__global__ void f2bf_k(const float* __restrict__ s, __nv_bfloat16* __restrict__ d, int n) {
    int i = blockIdx.x * 256 + threadIdx.x;
    if (i < n) d[i] = __float2bfloat16(s[i]);
}
__global__ void f2fp8_k(const float* __restrict__ s, uint8_t* __restrict__ d, float sc, int n) {
    int i = blockIdx.x * 256 + threadIdx.x;
    if (i < n) d[i] = f2fp8(s[i] * sc);
}
__global__ void bf2fp8_k(const __nv_bfloat16* __restrict__ s, uint8_t* __restrict__ d, float sc, int n) {
    int i = blockIdx.x * 256 + threadIdx.x;
    if (i < n) d[i] = f2fp8(__bfloat162float(s[i]) * sc);
}

__global__ void rmsnorm_k(const float* __restrict__ x, const float* __restrict__ w) {
    int row = blockIdx.x;
    int tid = threadIdx.x;
    const float* xr = x + (size_t)row * D_MODEL;
    float s = 0.f;
    for (int i = tid; i < D_MODEL; i += 256) { float v = xr[i]; s += v * v; }
    __shared__ float red[256];
    red[tid] = s; __syncthreads();
    for (int o = 128; o > 0; o >>= 1) {
        if (tid < o) red[tid] += red[tid + o];
        __syncthreads();
    }
    float scale = rsqrtf(red[0] / (float)D_MODEL + 1e-6f) * S_XN;
    for (int i = tid; i < D_MODEL; i += 256)
        g_xn8[(size_t)row * D_MODEL + i] = f2fp8(xr[i] * w[i] * scale);
}

// 32x32 tiled transpose: g_pwT[c][o] = pw_w[o][c], fp32 -> bf16
__global__ void transpose_pw_k(const float* __restrict__ src) {
    __shared__ float t[32][33];
    int bx = blockIdx.x * 32, by = blockIdx.y * 32;
    int tx = threadIdx.x, ty = threadIdx.y;
    #pragma unroll
    for (int i = 0; i < 32; i += 8)
        t[ty + i][tx] = src[(size_t)(by + ty + i) * DI + bx + tx];
    __syncthreads();
    #pragma unroll
    for (int i = 0; i < 32; i += 8)
        g_pwT[(size_t)(bx + ty + i) * DI + by + tx] = __float2bfloat16(t[tx][ty + i]);
}

// fused depthwise convs: ca (4-tap, bf16) and cb8 = fp8(silu(9-tap) * S_CB)
#define CL 128
#define CD 64
__global__ void __launch_bounds__(256) conv_fused_k(
    const float* __restrict__ ka, const float* __restrict__ ba,
    const float* __restrict__ ks, const float* __restrict__ bs)
{
    __shared__ __nv_bfloat16 sv[CL + 8][CD];
    int d0 = blockIdx.x * CD;
    int l0 = blockIdx.y * CL;
    int b  = blockIdx.z;
    const __nv_bfloat16* vb = g_val + (size_t)b * L_SEQ * DI;
    int tid = threadIdx.x;
    for (int i = tid; i < (CL + 8) * 8; i += 256) {
        int r = i >> 3, s = i & 7;
        int l = l0 - 4 + r;
        uint4 v = make_uint4(0, 0, 0, 0);
        if (l >= 0 && l < L_SEQ)
            v = *(const uint4*)(vb + (size_t)l * DI + d0 + s * 8);
        *(uint4*)(&sv[r][s * 8]) = v;
    }
    __syncthreads();
    int d = tid & (CD - 1);
    int lw = tid >> 6;
    float wa[4], w9[9];
    #pragma unroll
    for (int j = 0; j < 4; j++) wa[j] = ka[(d0 + d) * 4 + j];
    #pragma unroll
    for (int j = 0; j < 9; j++) w9[j] = ks[(d0 + d) * 9 + j];
    float bav = ba[d0 + d], bsv = bs[d0 + d];
    for (int li = 0; li < CL / 4; li++) {
        int l = lw * (CL / 4) + li;
        float aa = bav, ab = bsv;
        #pragma unroll
        for (int j = 0; j < 4; j++) aa += __bfloat162float(sv[l + 3 + j][d]) * wa[j];
        #pragma unroll
        for (int j = 0; j < 9; j++) ab += __bfloat162float(sv[l + j][d]) * w9[j];
        size_t o = ((size_t)b * L_SEQ + l0 + l) * DI + d0 + d;
        g_ca[o] = __float2bfloat16(aa);
        float sg = 1.f / (1.f + __expf(-ab));
        g_cb8[o] = f2fp8(ab * sg * S_CB);
    }
}

// T[s][n] = sum_d Bm[s,d] * ha_w[n,d]
__global__ void compute_T_k(const float* __restrict__ Bm, const float* __restrict__ haw) {
    int n = blockIdx.x;
    int tid = threadIdx.x;
    float acc[DS];
    #pragma unroll
    for (int s = 0; s < DS; s++) acc[s] = 0.f;
    for (int d = tid; d < DI; d += 128) {
        float h = haw[(size_t)n * DI + d];
        #pragma unroll
        for (int s = 0; s < DS; s++) acc[s] += h * Bm[s * DI + d];
    }
    __shared__ float red[DS * 128];
    #pragma unroll
    for (int s = 0; s < DS; s++) red[s * 128 + tid] = acc[s];
    __syncthreads();
    if (tid < DS) {
        float t = 0.f;
        for (int i = 0; i < 128; i++) t += red[tid * 128 + i];
        g_T[tid * DH + n] = t;
    }
}

// a1[m, 0:16] = S_YC * sum_d ca[m,d] * A[d,s]; zero bytes 16..63. One warp per token.
__global__ void __launch_bounds__(256) a1_k(const float* __restrict__ A) {
    int warp = threadIdx.x >> 5, lane = threadIdx.x & 31;
    size_t m = (size_t)blockIdx.x * 8 + warp;
    const __nv_bfloat16* car = g_ca + m * DI;
    float acc[16];
    #pragma unroll
    for (int s = 0; s < 16; s++) acc[s] = 0.f;
    for (int d = lane; d < DI; d += 32) {
        float c = __bfloat162float(car[d]);
        const float4* Ar = (const float4*)(A + (size_t)d * 16);
        float4 a0 = Ar[0], a1v = Ar[1], a2 = Ar[2], a3 = Ar[3];
        acc[0]  += c * a0.x;  acc[1]  += c * a0.y;  acc[2]  += c * a0.z;  acc[3]  += c * a0.w;
        acc[4]  += c * a1v.x; acc[5]  += c * a1v.y; acc[6]  += c * a1v.z; acc[7]  += c * a1v.w;
        acc[8]  += c * a2.x;  acc[9]  += c * a2.y;  acc[10] += c * a2.z;  acc[11] += c * a2.w;
        acc[12] += c * a3.x;  acc[13] += c * a3.y;  acc[14] += c * a3.z;  acc[15] += c * a3.w;
    }
    #pragma unroll
    for (int s = 0; s < 16; s++)
        #pragma unroll
        for (int o = 16; o > 0; o >>= 1)
            acc[s] += __shfl_xor_sync(0xFFFFFFFFu, acc[s], o);
    if (lane == 0) {
        uint32_t w[4];
        #pragma unroll
        for (int h = 0; h < 4; h++) {
            uint32_t lo = f2fp8x2(acc[4 * h] * S_YC, acc[4 * h + 1] * S_YC);
            uint32_t hi = f2fp8x2(acc[4 * h + 2] * S_YC, acc[4 * h + 3] * S_YC);
            w[h] = lo | (hi << 16);
        }
        uint4* dst = (uint4*)(g_yc8 + m * YK8);
        dst[0] = make_uint4(w[0], w[1], w[2], w[3]);
        dst[1] = make_uint4(0, 0, 0, 0);
        dst[2] = make_uint4(0, 0, 0, 0);
        dst[3] = make_uint4(0, 0, 0, 0);
    }
}

// wf8[n][s] = fp8(S_W * sum_t T[s,t]*fuse_w[n,t]); bytes 16..63 zero
__global__ void wf_u_k(const float* __restrict__ fw) {
    int n = blockIdx.x;
    int tid = threadIdx.x;   // 128
    float acc[DS];
    #pragma unroll
    for (int s = 0; s < DS; s++) acc[s] = 0.f;
    for (int t = tid; t < DH; t += 128) {
        float f = fw[(size_t)n * DI + t];
        #pragma unroll
        for (int s = 0; s < DS; s++) acc[s] += f * g_T[s * DH + t];
    }
    __shared__ float red[DS * 128];
    #pragma unroll
    for (int s = 0; s < DS; s++) red[s * 128 + tid] = acc[s];
    __syncthreads();
    if (tid < DS) {
        float t = 0.f;
        for (int i = 0; i < 128; i++) t += red[tid * 128 + i];
        g_wf8[(size_t)n * YK8 + tid] = f2fp8(t * S_W);
    } else if (tid < 64) {
        g_wf8[(size_t)n * YK8 + tid] = 0;
    }
}

// wf8[n][64+j] = fp8(S_W * fuse_w[n][1024+j])
__global__ void wf_copy_k(const float* __restrict__ fw) {
    int idx = blockIdx.x * 256 + threadIdx.x;      // DI * DH
    int n = idx >> 10, j = idx & 1023;
    g_wf8[(size_t)n * YK8 + 64 + j] = f2fp8(fw[(size_t)n * DI + DH + j] * S_W);
}

// biasy[n] = fuse_b[n] + sum_{t<1024} fuse_w[n,t] * ha_b[t]
__global__ void bias_y_k(const float* __restrict__ fw, const float* __restrict__ hab,
                         const float* __restrict__ fb) {
    int n = blockIdx.x;
    int tid = threadIdx.x;
    float a = 0.f;
    for (int t = tid; t < DH; t += 256) a += fw[(size_t)n * DI + t] * hab[t];
    __shared__ float red[256];
    red[tid] = a; __syncthreads();
    for (int o = 128; o > 0; o >>= 1) {
        if (tid < o) red[tid] += red[tid + o];
        __syncthreads();
    }
    if (tid == 0) g_biasy[n] = red[0] + fb[n];
}

// bias_b[n] = hb_b[n] + sum_d hb_w[n,d]*pw_b[d]
__global__ void bias_b_k(const float* __restrict__ hbw, const float* __restrict__ pwb,
                         const float* __restrict__ hbb) {
    int n = blockIdx.x;
    int tid = threadIdx.x;
    float a = 0.f;
    for (int d = tid; d < DI; d += 256) a += hbw[(size_t)n * DI + d] * pwb[d];
    __shared__ float red[256];
    red[tid] = a; __syncthreads();
    for (int o = 128; o > 0; o >>= 1) {
        if (tid < o) red[tid] += red[tid + o];
        __syncthreads();
    }
    if (tid == 0) g_biasb[n] = red[0] + hbb[n];
}

// ---------------- launch ----------------
static void* sym_addr(const void* s) {
    void* p = nullptr;
    cudaGetSymbolAddress(&p, s);
    return p;
}

extern "C" void kernel_launch(void* const* d_in, const int* in_sizes, int n_in,
                              void* d_out, int out_size) {
    const float* x      = (const float*)d_in[0];
    const float* norm_w = (const float*)d_in[1];
    const float* in_w   = (const float*)d_in[2];
    const float* in_b   = (const float*)d_in[3];
    const float* dwa_k  = (const float*)d_in[4];
    const float* dwa_b  = (const float*)d_in[5];
    const float* A      = (const float*)d_in[6];
    const float* Bm     = (const float*)d_in[7];
    const float* sym_k  = (const float*)d_in[8];
    const float* sym_b  = (const float*)d_in[9];
    const float* pw_w   = (const float*)d_in[10];
    const float* pw_b   = (const float*)d_in[11];
    const float* ha_w   = (const float*)d_in[12];
    const float* ha_b   = (const float*)d_in[13];
    const float* hb_w   = (const float*)d_in[14];
    const float* hb_b   = (const float*)d_in[15];
    const float* fuse_w = (const float*)d_in[16];
    const float* fuse_b = (const float*)d_in[17];
    const float* out_w  = (const float*)d_in[18];
    const float* out_b  = (const float*)d_in[19];

    uint8_t*       p_xn8   = (uint8_t*)sym_addr(g_xn8);
    __nv_bfloat16* p_gate  = (__nv_bfloat16*)sym_addr(g_gate);
    __nv_bfloat16* p_val   = (__nv_bfloat16*)sym_addr(g_val);
    __nv_bfloat16* p_ca    = (__nv_bfloat16*)sym_addr(g_ca);
    uint8_t*       p_cb8   = (uint8_t*)sym_addr(g_cb8);
    uint8_t*       p_yc8   = (uint8_t*)sym_addr(g_yc8);
    uint8_t*       p_f8    = (uint8_t*)sym_addr(g_f8);
    uint8_t*       p_inw8  = (uint8_t*)sym_addr(g_inw8);
    uint8_t*       p_inwq  = (uint8_t*)sym_addr(g_inwq);
    uint8_t*       p_outw8 = (uint8_t*)sym_addr(g_outw8);
    uint8_t*       p_outwq = (uint8_t*)sym_addr(g_outwq);
    uint8_t*       p_Wb8   = (uint8_t*)sym_addr(g_Wb8);
    uint8_t*       p_Wbq   = (uint8_t*)sym_addr(g_Wbq);
    uint8_t*       p_wf8   = (uint8_t*)sym_addr(g_wf8);
    uint8_t*       p_wfq   = (uint8_t*)sym_addr(g_wfq);
    __nv_bfloat16* p_hbw   = (__nv_bfloat16*)sym_addr(g_hbw);
    __nv_bfloat16* p_pwT   = (__nv_bfloat16*)sym_addr(g_pwT);
    __nv_bfloat16* p_Wb    = (__nv_bfloat16*)sym_addr(g_Wb);
    float*         p_biasb = (float*)sym_addr(g_biasb);
    float*         p_biasy = (float*)sym_addr(g_biasy);

    cudaFuncSetAttribute(mma_gemm_k, cudaFuncAttributeMaxDynamicSharedMemorySize, SMEM_TOTAL);
    cudaFuncSetAttribute(qgemm2_k<QEPI_INPROJ>, cudaFuncAttributeMaxDynamicSharedMemorySize, QSMEM2);
    cudaFuncSetAttribute(qgemm2_k<QEPI_FP8>,    cudaFuncAttributeMaxDynamicSharedMemorySize, QSMEM2);
    cudaFuncSetAttribute(qgemm2_k<QEPI_GATE>,   cudaFuncAttributeMaxDynamicSharedMemorySize, QSMEM2);
    cudaFuncSetAttribute(qgemm2_k<QEPI_RESID>,  cudaFuncAttributeMaxDynamicSharedMemorySize, QSMEM2);

    auto cgrid = [](int n) { return (n + 255) / 256; };

    const float INV_IN  = 1.f / (S_XN * S_W);     // gate/val
    const float INV_BH  = 1.f / (S_CB * S_W);     // b_h
    const float INV_Y   = 1.f / (S_YC * S_W);     // y
    const float INV_OUT = 1.f / (S_F * S_W);      // out

    // launch order: #4 (1-based) = merged in_proj qgemm2 -> profiled by ncu
    rmsnorm_k<<<M_TOK, 256>>>(x, norm_w);                                           // 1
    f2fp8_k<<<cgrid(2 * DI * D_MODEL), 256>>>(in_w, p_inw8, S_W, 2 * DI * D_MODEL); // 2
    shuffleB_k<<<cgrid(2 * DI * D_MODEL / 4), 256>>>(p_inw8, p_inwq, 2 * DI, D_MODEL); // 3

    // merged in_proj: gate (sigmoid) | val, N=4096
    qgemm2_k<QEPI_INPROJ><<<dim3(4096 / BN, M_TOK / BM), 256, QSMEM2>>>(              // 4
        p_xn8, p_inwq, in_b, p_gate, p_val, DI,
        nullptr, nullptr, D_MODEL, (2 * DI) / 8, INV_IN, 0.f);

    f2bf_k<<<cgrid(DH * DI), 256>>>(hb_w, p_hbw, DH * DI);
    transpose_pw_k<<<dim3(DI / 32, DI / 32), dim3(32, 8)>>>(pw_w);

    conv_fused_k<<<dim3(DI / CD, L_SEQ / CL, 4), 256>>>(dwa_k, dwa_b, sym_k, sym_b);

    // folded-weight precomputes
    compute_T_k<<<DH, 128>>>(Bm, ha_w);
    mma_gemm_k<<<dim3(DI / BN, DH / BM), 256, SMEM_TOTAL>>>(p_hbw, p_pwT, p_Wb, DI, DI);
    bf2fp8_k<<<cgrid(DH * DI), 256>>>(p_Wb, p_Wb8, S_W, DH * DI);
    shuffleB_k<<<cgrid(DH * DI / 4), 256>>>(p_Wb8, p_Wbq, DH, DI);
    bias_b_k<<<DH, 256>>>(hb_w, pw_b, hb_b);
    wf_u_k<<<DI, 128>>>(fuse_w);
    wf_copy_k<<<cgrid(DI * DH), 256>>>(fuse_w);
    shuffleB_k<<<cgrid(DI * YK8 / 4), 256>>>(p_wf8, p_wfq, DI, YK8);
    bias_y_k<<<DI, 256>>>(fuse_w, ha_b, fuse_b);
    f2fp8_k<<<cgrid(D_MODEL * DI), 256>>>(out_w, p_outw8, S_W, D_MODEL * DI);
    shuffleB_k<<<cgrid(D_MODEL * DI / 4), 256>>>(p_outw8, p_outwq, D_MODEL, DI);

    // a-branch through rank-16 bottleneck
    a1_k<<<M_TOK / 8, 256>>>(A);

    // b-branch: b_h = cb @ Wb + biasb  (fp8 out into yc bytes 64..1087)
    qgemm2_k<QEPI_FP8><<<dim3(DH / BN, M_TOK / BM), 256, QSMEM2>>>(
        p_cb8, p_Wbq, p_biasb, p_yc8 + 64, nullptr, YK8,
        nullptr, nullptr, DI, DH / 8, INV_BH, S_YC);

    // fused y GEMM: y = [a1|b_h] @ wf^T + biasy, gated (K=1088 fp8)
    qgemm2_k<QEPI_GATE><<<dim3(DI / BN, M_TOK / BM), 256, QSMEM2>>>(
        p_yc8, p_wfq, p_biasy, p_f8, nullptr, DI,
        p_gate, nullptr, YK8, DI / 8, INV_Y, S_F);

    // out projection (+ residual), fp32 output
    qgemm2_k<QEPI_RESID><<<dim3(D_MODEL / BN, M_TOK / BM), 256, QSMEM2>>>(
        p_f8, p_outwq, out_b, d_out, nullptr, D_MODEL,
        nullptr, x, DI, D_MODEL / 8, INV_OUT, 0.f);
}

// round 17
// speedup vs baseline: 1.2210x; 1.2210x over previous
#include <cuda_runtime.h>
#include <cuda_bf16.h>
#include <cuda_fp8.h>
#include <cstdint>

#define M_TOK   16384
#define L_SEQ   4096
#define D_MODEL 1024
#define DI      2048
#define DS      16
#define DH      1024
#define YK8     1088          // fp8 concat K: 16 a1 + 48 pad + 1024 b_h

// scale factors (power-of-2)
#define S_XN  4.0f
#define S_W   128.0f
#define S_CB  64.0f
#define S_YC  64.0f
#define S_F   256.0f

// ---------------- bf16 GEMM tiling (Wb precompute only) ----------------
#define BM 128
#define BN 128
#define PITCH 40
#define STAGE_BYTES (128 * PITCH * 2)            // 10240
#define NSTAGE 4
#define SMEM_TOTAL (NSTAGE * 2 * STAGE_BYTES)    // 81920

// ---------------- fp8 GEMM tiling ----------------
#define QPITCH 80                                 // bytes per smem row
#define QSTAGE (128 * QPITCH)                     // 10240
#define QSMEM_TOTAL (NSTAGE * 2 * QSTAGE)         // 81920

// ---------------- scratch (device globals) ----------------
__device__ __align__(16) uint8_t g_xn8 [(size_t)M_TOK * D_MODEL];
__device__ __nv_bfloat16 g_gate[(size_t)M_TOK * DI];
__device__ __nv_bfloat16 g_val [(size_t)M_TOK * DI];
__device__ __align__(16) uint8_t g_cb8 [(size_t)M_TOK * DI];
__device__ __align__(16) uint8_t g_yc8 [(size_t)M_TOK * YK8];
__device__ __align__(16) uint8_t g_f8  [(size_t)M_TOK * DI];
__device__ float         g_a1f [(size_t)M_TOK * DS];

__device__ __align__(16) uint8_t g_inw8 [(size_t)2 * DI * D_MODEL];
__device__ __align__(16) uint8_t g_outw8[(size_t)D_MODEL * DI];
__device__ __align__(16) uint8_t g_Wb8  [(size_t)DH * DI];
__device__ __align__(16) uint8_t g_wf8  [(size_t)DI * YK8];
__device__ __nv_bfloat16 g_hbw  [(size_t)DH * DI];
__device__ __nv_bfloat16 g_pwT  [(size_t)DI * DI];
__device__ __nv_bfloat16 g_Wb   [(size_t)DH * DI];
__device__ float         g_T    [DS * DH];
__device__ float         g_biasb[DH];
__device__ float         g_biasy[DI];

// ---------------- PTX helpers ----------------
__device__ __forceinline__ uint32_t smem_u32(const void* p) {
    uint32_t a;
    asm("{ .reg .u64 t; cvta.to.shared.u64 t, %1; cvt.u32.u64 %0, t; }" : "=r"(a) : "l"(p));
    return a;
}
__device__ __forceinline__ void cpasync16(uint32_t dst, const void* src) {
    asm volatile("cp.async.cg.shared.global [%0], [%1], 16;" :: "r"(dst), "l"(src));
}
#define CP_COMMIT() asm volatile("cp.async.commit_group;" ::: "memory")
#define CP_WAIT2()  asm volatile("cp.async.wait_group 2;" ::: "memory")
#define CP_WAIT0()  asm volatile("cp.async.wait_group 0;" ::: "memory")

__device__ __forceinline__ void ldsm4(uint32_t* r, uint32_t addr) {
    asm volatile("ldmatrix.sync.aligned.m8n8.x4.shared.b16 {%0,%1,%2,%3}, [%4];"
        : "=r"(r[0]), "=r"(r[1]), "=r"(r[2]), "=r"(r[3]) : "r"(addr));
}
__device__ __forceinline__ void ldsm2(uint32_t* r, uint32_t addr) {
    asm volatile("ldmatrix.sync.aligned.m8n8.x2.shared.b16 {%0,%1}, [%2];"
        : "=r"(r[0]), "=r"(r[1]) : "r"(addr));
}
__device__ __forceinline__ void mma16816(float* d, const uint32_t* a, const uint32_t* b) {
    asm volatile("mma.sync.aligned.m16n8k16.row.col.f32.bf16.bf16.f32 "
        "{%0,%1,%2,%3}, {%4,%5,%6,%7}, {%8,%9}, {%0,%1,%2,%3};"
        : "+f"(d[0]), "+f"(d[1]), "+f"(d[2]), "+f"(d[3])
        : "r"(a[0]), "r"(a[1]), "r"(a[2]), "r"(a[3]), "r"(b[0]), "r"(b[1]));
}
__device__ __forceinline__ void qmma16832(float* d, const uint32_t* a, const uint32_t* b) {
    asm volatile("mma.sync.aligned.m16n8k32.row.col.f32.e4m3.e4m3.f32 "
        "{%0,%1,%2,%3}, {%4,%5,%6,%7}, {%8,%9}, {%0,%1,%2,%3};"
        : "+f"(d[0]), "+f"(d[1]), "+f"(d[2]), "+f"(d[3])
        : "r"(a[0]), "r"(a[1]), "r"(a[2]), "r"(a[3]), "r"(b[0]), "r"(b[1]));
}

__device__ __forceinline__ uint8_t f2fp8(float v) {
    return (uint8_t)__nv_cvt_float_to_fp8(v, __NV_SATFINITE, __NV_E4M3);
}
__device__ __forceinline__ uint16_t f2fp8x2(float a, float b) {
    return (uint16_t)__nv_cvt_float2_to_fp8x2(make_float2(a, b), __NV_SATFINITE, __NV_E4M3);
}

// ================= bf16 GEMM (Wb precompute only) =================
__global__ void __launch_bounds__(256, 2) mma_gemm_k(
    const __nv_bfloat16* __restrict__ X, const __nv_bfloat16* __restrict__ W,
    __nv_bfloat16* __restrict__ outp, int out_stride, int K)
{
    extern __shared__ char smem[];
    uint32_t sA = smem_u32(smem);
    uint32_t sB = sA + NSTAGE * STAGE_BYTES;
    int tid = threadIdx.x, warp = tid >> 5, lane = tid & 31;
    int wm = warp >> 2, wn = warp & 3;
    int bm = blockIdx.y * BM, bn = blockIdx.x * BN;
    int NC = K / 32;

    float acc[4][4][4];
    #pragma unroll
    for (int mi = 0; mi < 4; mi++)
        #pragma unroll
        for (int ni = 0; ni < 4; ni++)
            #pragma unroll
            for (int e = 0; e < 4; e++) acc[mi][ni][e] = 0.f;

    auto stage_load = [&](int st, int c) {
        uint32_t a = sA + st * STAGE_BYTES;
        uint32_t b = sB + st * STAGE_BYTES;
        int k0 = c * 32;
        #pragma unroll
        for (int it = 0; it < 2; it++) {
            int id = tid + it * 256;
            int r = id >> 2, s = id & 3;
            uint32_t off = (uint32_t)(r * PITCH + s * 8) * 2;
            cpasync16(a + off, X + (size_t)(bm + r) * K + k0 + s * 8);
            cpasync16(b + off, W + (size_t)(bn + r) * K + k0 + s * 8);
        }
    };

    #pragma unroll
    for (int c = 0; c < NSTAGE - 1; c++) { stage_load(c, c); CP_COMMIT(); }

    for (int c = 0; c < NC; c++) {
        int st = c & (NSTAGE - 1);
        CP_WAIT2();
        __syncthreads();
        if (c + NSTAGE - 1 < NC) stage_load((c + NSTAGE - 1) & (NSTAGE - 1), c + NSTAGE - 1);
        CP_COMMIT();

        uint32_t aBase = sA + st * STAGE_BYTES;
        uint32_t bBase = sB + st * STAGE_BYTES;
        #pragma unroll
        for (int kk = 0; kk < 2; kk++) {
            uint32_t af[4][4], bf[4][2];
            #pragma unroll
            for (int mi = 0; mi < 4; mi++) {
                int row = wm * 64 + mi * 16 + (lane & 15);
                ldsm4(af[mi], aBase + (uint32_t)(row * PITCH + kk * 16 + (lane >> 4) * 8) * 2);
            }
            #pragma unroll
            for (int ni = 0; ni < 4; ni++) {
                int row = wn * 32 + ni * 8 + (lane & 7);
                ldsm2(bf[ni], bBase + (uint32_t)(row * PITCH + kk * 16 + ((lane >> 3) & 1) * 8) * 2);
            }
            #pragma unroll
            for (int mi = 0; mi < 4; mi++)
                #pragma unroll
                for (int ni = 0; ni < 4; ni++)
                    mma16816(acc[mi][ni], af[mi], bf[ni]);
        }
    }
    CP_WAIT0();

    #pragma unroll
    for (int mi = 0; mi < 4; mi++)
        #pragma unroll
        for (int ni = 0; ni < 4; ni++) {
            int gn = bn + wn * 32 + ni * 8 + (lane & 3) * 2;
            #pragma unroll
            for (int h = 0; h < 2; h++) {
                int gm = bm + wm * 64 + mi * 16 + (lane >> 2) + h * 8;
                *(__nv_bfloat162*)(outp + (size_t)gm * out_stride + gn) =
                    __floats2bfloat162_rn(acc[mi][ni][h * 2], acc[mi][ni][h * 2 + 1]);
            }
        }
}

// ================= fp8 GEMM (R15 smem-B path) =================
enum { QEPI_INPROJ = 0, QEPI_FP8 = 1, QEPI_GATE = 2, QEPI_RESID = 3 };

template<int EPI>
__global__ void __launch_bounds__(256, 2) qgemm_k(
    const uint8_t* __restrict__ X, const uint8_t* __restrict__ W,
    const float* __restrict__ bias, void* __restrict__ outp, void* __restrict__ outp2,
    int ostride,
    const __nv_bfloat16* __restrict__ gate, const float* __restrict__ resid,
    int Kb, float inv_s, float s_out)
{
    extern __shared__ char smem[];
    uint32_t sA = smem_u32(smem);
    uint32_t sB = sA + NSTAGE * QSTAGE;
    int tid = threadIdx.x, warp = tid >> 5, lane = tid & 31;
    int wm = warp >> 2, wn = warp & 3;
    int bm = blockIdx.y * BM, bn = blockIdx.x * BN;
    int NC = Kb / 64;

    float acc[4][4][4];
    #pragma unroll
    for (int mi = 0; mi < 4; mi++)
        #pragma unroll
        for (int ni = 0; ni < 4; ni++)
            #pragma unroll
            for (int e = 0; e < 4; e++) acc[mi][ni][e] = 0.f;

    auto stage_load = [&](int st, int c) {
        uint32_t a = sA + st * QSTAGE;
        uint32_t b = sB + st * QSTAGE;
        int k0 = c * 64;
        #pragma unroll
        for (int it = 0; it < 2; it++) {
            int id = tid + it * 256;
            int r = id >> 2, s = id & 3;
            uint32_t off = (uint32_t)(r * QPITCH + s * 16);
            cpasync16(a + off, X + (size_t)(bm + r) * Kb + k0 + s * 16);
            cpasync16(b + off, W + (size_t)(bn + r) * Kb + k0 + s * 16);
        }
    };

    #pragma unroll
    for (int c = 0; c < NSTAGE - 1; c++) { stage_load(c, c); CP_COMMIT(); }

    for (int c = 0; c < NC; c++) {
        int st = c & (NSTAGE - 1);
        CP_WAIT2();
        __syncthreads();
        if (c + NSTAGE - 1 < NC) stage_load((c + NSTAGE - 1) & (NSTAGE - 1), c + NSTAGE - 1);
        CP_COMMIT();

        uint32_t aBase = sA + st * QSTAGE;
        uint32_t bBase = sB + st * QSTAGE;
        #pragma unroll
        for (int kk = 0; kk < 2; kk++) {
            uint32_t af[4][4], bf[4][2];
            #pragma unroll
            for (int mi = 0; mi < 4; mi++) {
                int row = wm * 64 + mi * 16 + (lane & 15);
                ldsm4(af[mi], aBase + (uint32_t)(row * QPITCH + kk * 32 + (lane >> 4) * 16));
            }
            #pragma unroll
            for (int ni = 0; ni < 4; ni++) {
                int row = wn * 32 + ni * 8 + (lane & 7);
                ldsm2(bf[ni], bBase + (uint32_t)(row * QPITCH + kk * 32 + ((lane >> 3) & 1) * 16));
            }
            #pragma unroll
            for (int mi = 0; mi < 4; mi++)
                #pragma unroll
                for (int ni = 0; ni < 4; ni++)
                    qmma16832(acc[mi][ni], af[mi], bf[ni]);
        }
    }
    CP_WAIT0();

    // -------- epilogue --------
    #pragma unroll
    for (int mi = 0; mi < 4; mi++) {
        #pragma unroll
        for (int ni = 0; ni < 4; ni++) {
            int gn = bn + wn * 32 + ni * 8 + (lane & 3) * 2;
            float bv0 = 0.f, bv1 = 0.f;
            if (bias) { bv0 = bias[gn]; bv1 = bias[gn + 1]; }
            #pragma unroll
            for (int h = 0; h < 2; h++) {
                int gm = bm + wm * 64 + mi * 16 + (lane >> 2) + h * 8;
                float v0 = acc[mi][ni][h * 2 + 0] * inv_s + bv0;
                float v1 = acc[mi][ni][h * 2 + 1] * inv_s + bv1;
                if (EPI == QEPI_INPROJ) {
                    if (gn < DI) {       // gate half: sigmoid -> bf16
                        v0 = 1.f / (1.f + __expf(-v0));
                        v1 = 1.f / (1.f + __expf(-v1));
                        *(__nv_bfloat162*)((__nv_bfloat16*)outp + (size_t)gm * DI + gn) =
                            __floats2bfloat162_rn(v0, v1);
                    } else {             // val half: bf16
                        *(__nv_bfloat162*)((__nv_bfloat16*)outp2 + (size_t)gm * DI + gn - DI) =
                            __floats2bfloat162_rn(v0, v1);
                    }
                } else if (EPI == QEPI_FP8) {
                    uint8_t* op = (uint8_t*)outp + (size_t)gm * ostride + gn;
                    *(uint16_t*)op = f2fp8x2(v0 * s_out, v1 * s_out);
                } else if (EPI == QEPI_GATE) {
                    __nv_bfloat162 g2 = *(const __nv_bfloat162*)(gate + (size_t)gm * DI + gn);
                    v0 *= __bfloat162float(g2.x);
                    v1 *= __bfloat162float(g2.y);
                    uint8_t* op = (uint8_t*)outp + (size_t)gm * ostride + gn;
                    *(uint16_t*)op = f2fp8x2(v0 * s_out, v1 * s_out);
                } else {  // QEPI_RESID
                    const float* rp = resid + (size_t)gm * ostride + gn;
                    float* op = (float*)outp + (size_t)gm * ostride + gn;
                    float2 r2 = *(const float2*)rp;
                    float2 o2; o2.x = v0 + r2.x; o2.y = v1 + r2.y;
                    *(float2*)op = o2;
                }
            }
        }
    }
}

// ---------------- small kernels ----------------
__global__ void f2bf_k(const float* __restrict__ s, __nv_bfloat16* __restrict__ d, int n) {
    int i = blockIdx.x * 256 + threadIdx.x;
    if (i < n) d[i] = __float2bfloat16(s[i]);
}
__global__ void f2fp8_k(const float* __restrict__ s, uint8_t* __restrict__ d, float sc, int n) {
    int i = blockIdx.x * 256 + threadIdx.x;
    if (i < n) d[i] = f2fp8(s[i] * sc);
}
__global__ void bf2fp8_k(const __nv_bfloat16* __restrict__ s, uint8_t* __restrict__ d, float sc, int n) {
    int i = blockIdx.x * 256 + threadIdx.x;
    if (i < n) d[i] = f2fp8(__bfloat162float(s[i]) * sc);
}
__global__ void zero_a1_k() {
    ((float4*)g_a1f)[blockIdx.x * 256 + threadIdx.x] = make_float4(0.f, 0.f, 0.f, 0.f);
}

__global__ void rmsnorm_k(const float* __restrict__ x, const float* __restrict__ w) {
    int row = blockIdx.x;
    int tid = threadIdx.x;
    const float* xr = x + (size_t)row * D_MODEL;
    float s = 0.f;
    for (int i = tid; i < D_MODEL; i += 256) { float v = xr[i]; s += v * v; }
    __shared__ float red[256];
    red[tid] = s; __syncthreads();
    for (int o = 128; o > 0; o >>= 1) {
        if (tid < o) red[tid] += red[tid + o];
        __syncthreads();
    }
    float scale = rsqrtf(red[0] / (float)D_MODEL + 1e-6f) * S_XN;
    for (int i = tid; i < D_MODEL; i += 256)
        g_xn8[(size_t)row * D_MODEL + i] = f2fp8(xr[i] * w[i] * scale);
}

// 32x32 tiled transpose: g_pwT[c][o] = pw_w[o][c], fp32 -> bf16
__global__ void transpose_pw_k(const float* __restrict__ src) {
    __shared__ float t[32][33];
    int bx = blockIdx.x * 32, by = blockIdx.y * 32;
    int tx = threadIdx.x, ty = threadIdx.y;
    #pragma unroll
    for (int i = 0; i < 32; i += 8)
        t[ty + i][tx] = src[(size_t)(by + ty + i) * DI + bx + tx];
    __syncthreads();
    #pragma unroll
    for (int i = 0; i < 32; i += 8)
        g_pwT[(size_t)(bx + ty + i) * DI + by + tx] = __float2bfloat16(t[tx][ty + i]);
}

// fused depthwise convs + a1 reduction:
//   cb8 = fp8(silu(9-tap) * S_CB)
//   a1f[m][s] += sum_d aa[m,d] * A[d,s]   (aa = 4-tap conv; never hits gmem)
#define CL 128
#define CD 64
__global__ void __launch_bounds__(256) conv_fused_k(
    const float* __restrict__ ka, const float* __restrict__ ba,
    const float* __restrict__ ks, const float* __restrict__ bs,
    const float* __restrict__ A)
{
    __shared__ __nv_bfloat16 sv[CL + 8][CD];
    __shared__ __nv_bfloat16 sa[CL][CD];
    __shared__ float As[CD][DS];
    int d0 = blockIdx.x * CD;
    int l0 = blockIdx.y * CL;
    int b  = blockIdx.z;
    const __nv_bfloat16* vb = g_val + (size_t)b * L_SEQ * DI;
    int tid = threadIdx.x;
    for (int i = tid; i < (CL + 8) * 8; i += 256) {
        int r = i >> 3, s = i & 7;
        int l = l0 - 4 + r;
        uint4 v = make_uint4(0, 0, 0, 0);
        if (l >= 0 && l < L_SEQ)
            v = *(const uint4*)(vb + (size_t)l * DI + d0 + s * 8);
        *(uint4*)(&sv[r][s * 8]) = v;
    }
    for (int i = tid; i < CD * DS; i += 256)
        As[i >> 4][i & 15] = A[(size_t)(d0 + (i >> 4)) * DS + (i & 15)];
    __syncthreads();

    int d = tid & (CD - 1);
    int lw = tid >> 6;
    float wa[4], w9[9];
    #pragma unroll
    for (int j = 0; j < 4; j++) wa[j] = ka[(d0 + d) * 4 + j];
    #pragma unroll
    for (int j = 0; j < 9; j++) w9[j] = ks[(d0 + d) * 9 + j];
    float bav = ba[d0 + d], bsv = bs[d0 + d];
    for (int li = 0; li < CL / 4; li++) {
        int l = lw * (CL / 4) + li;
        float aa = bav, ab = bsv;
        #pragma unroll
        for (int j = 0; j < 4; j++) aa += __bfloat162float(sv[l + 3 + j][d]) * wa[j];
        #pragma unroll
        for (int j = 0; j < 9; j++) ab += __bfloat162float(sv[l + j][d]) * w9[j];
        sa[l][d] = __float2bfloat16(aa);
        float sg = 1.f / (1.f + __expf(-ab));
        g_cb8[((size_t)b * L_SEQ + l0 + l) * DI + d0 + d] = f2fp8(ab * sg * S_CB);
    }
    __syncthreads();

    // a1 partial: thread t handles l = t>>1, s-range (t&1)*8 .. +7
    int l = tid >> 1;
    int s0 = (tid & 1) * 8;
    float acc[8];
    #pragma unroll
    for (int s = 0; s < 8; s++) acc[s] = 0.f;
    #pragma unroll 8
    for (int dd = 0; dd < CD; dd++) {
        float av = __bfloat162float(sa[l][dd]);
        #pragma unroll
        for (int s = 0; s < 8; s++) acc[s] += av * As[dd][s0 + s];
    }
    size_t m = (size_t)b * L_SEQ + l0 + l;
    #pragma unroll
    for (int s = 0; s < 8; s++)
        atomicAdd(&g_a1f[m * DS + s0 + s], acc[s]);
}

// quantize a1 -> yc8[0:16], zero pad bytes 16..63
__global__ void a1_store_k() {
    size_t m = (size_t)blockIdx.x * 256 + threadIdx.x;
    const float* a = g_a1f + m * DS;
    uint32_t w[4];
    #pragma unroll
    for (int h = 0; h < 4; h++) {
        uint32_t lo = f2fp8x2(a[4 * h] * S_YC, a[4 * h + 1] * S_YC);
        uint32_t hi = f2fp8x2(a[4 * h + 2] * S_YC, a[4 * h + 3] * S_YC);
        w[h] = lo | (hi << 16);
    }
    uint4* dst = (uint4*)(g_yc8 + m * YK8);
    dst[0] = make_uint4(w[0], w[1], w[2], w[3]);
    dst[1] = make_uint4(0, 0, 0, 0);
    dst[2] = make_uint4(0, 0, 0, 0);
    dst[3] = make_uint4(0, 0, 0, 0);
}

// T[s][n] = sum_d Bm[s,d] * ha_w[n,d]
__global__ void compute_T_k(const float* __restrict__ Bm, const float* __restrict__ haw) {
    int n = blockIdx.x;
    int tid = threadIdx.x;
    float acc[DS];
    #pragma unroll
    for (int s = 0; s < DS; s++) acc[s] = 0.f;
    for (int d = tid; d < DI; d += 128) {
        float h = haw[(size_t)n * DI + d];
        #pragma unroll
        for (int s = 0; s < DS; s++) acc[s] += h * Bm[s * DI + d];
    }
    __shared__ float red[DS * 128];
    #pragma unroll
    for (int s = 0; s < DS; s++) red[s * 128 + tid] = acc[s];
    __syncthreads();
    if (tid < DS) {
        float t = 0.f;
        for (int i = 0; i < 128; i++) t += red[tid * 128 + i];
        g_T[tid * DH + n] = t;
    }
}

// wf8[n][s] = fp8(S_W * sum_t T[s,t]*fuse_w[n,t]); bytes 16..63 zero
__global__ void wf_u_k(const float* __restrict__ fw) {
    int n = blockIdx.x;
    int tid = threadIdx.x;   // 128
    float acc[DS];
    #pragma unroll
    for (int s = 0; s < DS; s++) acc[s] = 0.f;
    for (int t = tid; t < DH; t += 128) {
        float f = fw[(size_t)n * DI + t];
        #pragma unroll
        for (int s = 0; s < DS; s++) acc[s] += f * g_T[s * DH + t];
    }
    __shared__ float red[DS * 128];
    #pragma unroll
    for (int s = 0; s < DS; s++) red[s * 128 + tid] = acc[s];
    __syncthreads();
    if (tid < DS) {
        float t = 0.f;
        for (int i = 0; i < 128; i++) t += red[tid * 128 + i];
        g_wf8[(size_t)n * YK8 + tid] = f2fp8(t * S_W);
    } else if (tid < 64) {
        g_wf8[(size_t)n * YK8 + tid] = 0;
    }
}

// wf8[n][64+j] = fp8(S_W * fuse_w[n][1024+j])
__global__ void wf_copy_k(const float* __restrict__ fw) {
    int idx = blockIdx.x * 256 + threadIdx.x;      // DI * DH
    int n = idx >> 10, j = idx & 1023;
    g_wf8[(size_t)n * YK8 + 64 + j] = f2fp8(fw[(size_t)n * DI + DH + j] * S_W);
}

// biasy[n] = fuse_b[n] + sum_{t<1024} fuse_w[n,t] * ha_b[t]
__global__ void bias_y_k(const float* __restrict__ fw, const float* __restrict__ hab,
                         const float* __restrict__ fb) {
    int n = blockIdx.x;
    int tid = threadIdx.x;
    float a = 0.f;
    for (int t = tid; t < DH; t += 256) a += fw[(size_t)n * DI + t] * hab[t];
    __shared__ float red[256];
    red[tid] = a; __syncthreads();
    for (int o = 128; o > 0; o >>= 1) {
        if (tid < o) red[tid] += red[tid + o];
        __syncthreads();
    }
    if (tid == 0) g_biasy[n] = red[0] + fb[n];
}

// bias_b[n] = hb_b[n] + sum_d hb_w[n,d]*pw_b[d]
__global__ void bias_b_k(const float* __restrict__ hbw, const float* __restrict__ pwb,
                         const float* __restrict__ hbb) {
    int n = blockIdx.x;
    int tid = threadIdx.x;
    float a = 0.f;
    for (int d = tid; d < DI; d += 256) a += hbw[(size_t)n * DI + d] * pwb[d];
    __shared__ float red[256];
    red[tid] = a; __syncthreads();
    for (int o = 128; o > 0; o >>= 1) {
        if (tid < o) red[tid] += red[tid + o];
        __syncthreads();
    }
    if (tid == 0) g_biasb[n] = red[0] + hbb[n];
}

// ---------------- launch ----------------
static void* sym_addr(const void* s) {
    void* p = nullptr;
    cudaGetSymbolAddress(&p, s);
    return p;
}

extern "C" void kernel_launch(void* const* d_in, const int* in_sizes, int n_in,
                              void* d_out, int out_size) {
    const float* x      = (const float*)d_in[0];
    const float* norm_w = (const float*)d_in[1];
    const float* in_w   = (const float*)d_in[2];
    const float* in_b   = (const float*)d_in[3];
    const float* dwa_k  = (const float*)d_in[4];
    const float* dwa_b  = (const float*)d_in[5];
    const float* A      = (const float*)d_in[6];
    const float* Bm     = (const float*)d_in[7];
    const float* sym_k  = (const float*)d_in[8];
    const float* sym_b  = (const float*)d_in[9];
    const float* pw_w   = (const float*)d_in[10];
    const float* pw_b   = (const float*)d_in[11];
    const float* ha_w   = (const float*)d_in[12];
    const float* ha_b   = (const float*)d_in[13];
    const float* hb_w   = (const float*)d_in[14];
    const float* hb_b   = (const float*)d_in[15];
    const float* fuse_w = (const float*)d_in[16];
    const float* fuse_b = (const float*)d_in[17];
    const float* out_w  = (const float*)d_in[18];
    const float* out_b  = (const float*)d_in[19];

    uint8_t*       p_xn8   = (uint8_t*)sym_addr(g_xn8);
    __nv_bfloat16* p_gate  = (__nv_bfloat16*)sym_addr(g_gate);
    __nv_bfloat16* p_val   = (__nv_bfloat16*)sym_addr(g_val);
    uint8_t*       p_cb8   = (uint8_t*)sym_addr(g_cb8);
    uint8_t*       p_yc8   = (uint8_t*)sym_addr(g_yc8);
    uint8_t*       p_f8    = (uint8_t*)sym_addr(g_f8);
    uint8_t*       p_inw8  = (uint8_t*)sym_addr(g_inw8);
    uint8_t*       p_outw8 = (uint8_t*)sym_addr(g_outw8);
    uint8_t*       p_Wb8   = (uint8_t*)sym_addr(g_Wb8);
    uint8_t*       p_wf8   = (uint8_t*)sym_addr(g_wf8);
    __nv_bfloat16* p_hbw   = (__nv_bfloat16*)sym_addr(g_hbw);
    __nv_bfloat16* p_pwT   = (__nv_bfloat16*)sym_addr(g_pwT);
    __nv_bfloat16* p_Wb    = (__nv_bfloat16*)sym_addr(g_Wb);
    float*         p_biasb = (float*)sym_addr(g_biasb);
    float*         p_biasy = (float*)sym_addr(g_biasy);

    cudaFuncSetAttribute(mma_gemm_k, cudaFuncAttributeMaxDynamicSharedMemorySize, SMEM_TOTAL);
    cudaFuncSetAttribute(qgemm_k<QEPI_INPROJ>, cudaFuncAttributeMaxDynamicSharedMemorySize, QSMEM_TOTAL);
    cudaFuncSetAttribute(qgemm_k<QEPI_FP8>,    cudaFuncAttributeMaxDynamicSharedMemorySize, QSMEM_TOTAL);
    cudaFuncSetAttribute(qgemm_k<QEPI_GATE>,   cudaFuncAttributeMaxDynamicSharedMemorySize, QSMEM_TOTAL);
    cudaFuncSetAttribute(qgemm_k<QEPI_RESID>,  cudaFuncAttributeMaxDynamicSharedMemorySize, QSMEM_TOTAL);

    auto cgrid = [](int n) { return (n + 255) / 256; };

    const float INV_IN  = 1.f / (S_XN * S_W);     // gate/val
    const float INV_BH  = 1.f / (S_CB * S_W);     // b_h
    const float INV_Y   = 1.f / (S_YC * S_W);     // y
    const float INV_OUT = 1.f / (S_F * S_W);      // out

    // launch order: #4 (1-based) = merged in_proj -> profiled by ncu
    rmsnorm_k<<<M_TOK, 256>>>(x, norm_w);                                           // 1
    f2fp8_k<<<cgrid(2 * DI * D_MODEL), 256>>>(in_w, p_inw8, S_W, 2 * DI * D_MODEL); // 2
    zero_a1_k<<<(M_TOK * DS / 4) / 256, 256>>>();                                   // 3

    // merged in_proj: gate (sigmoid) | val, N=4096, K=1024
    qgemm_k<QEPI_INPROJ><<<dim3(2 * DI / BN, M_TOK / BM), 256, QSMEM_TOTAL>>>(      // 4
        p_xn8, p_inw8, in_b, p_gate, p_val, DI,
        nullptr, nullptr, D_MODEL, INV_IN, 0.f);

    f2bf_k<<<cgrid(DH * DI), 256>>>(hb_w, p_hbw, DH * DI);
    transpose_pw_k<<<dim3(DI / 32, DI / 32), dim3(32, 8)>>>(pw_w);

    // convs + fused a1 reduction (writes cb8 and a1f; no ca in gmem)
    conv_fused_k<<<dim3(DI / CD, L_SEQ / CL, 4), 256>>>(dwa_k, dwa_b, sym_k, sym_b, A);
    a1_store_k<<<M_TOK / 256, 256>>>();

    // folded-weight precomputes
    compute_T_k<<<DH, 128>>>(Bm, ha_w);
    mma_gemm_k<<<dim3(DI / BN, DH / BM), 256, SMEM_TOTAL>>>(p_hbw, p_pwT, p_Wb, DI, DI);
    bf2fp8_k<<<cgrid(DH * DI), 256>>>(p_Wb, p_Wb8, S_W, DH * DI);
    bias_b_k<<<DH, 256>>>(hb_w, pw_b, hb_b);
    wf_u_k<<<DI, 128>>>(fuse_w);
    wf_copy_k<<<cgrid(DI * DH), 256>>>(fuse_w);
    bias_y_k<<<DI, 256>>>(fuse_w, ha_b, fuse_b);
    f2fp8_k<<<cgrid(D_MODEL * DI), 256>>>(out_w, p_outw8, S_W, D_MODEL * DI);

    // b-branch: b_h = cb @ Wb + biasb  (fp8 out into yc bytes 64..1087)
    qgemm_k<QEPI_FP8><<<dim3(DH / BN, M_TOK / BM), 256, QSMEM_TOTAL>>>(
        p_cb8, p_Wb8, p_biasb, p_yc8 + 64, nullptr, YK8,
        nullptr, nullptr, DI, INV_BH, S_YC);

    // fused y GEMM: y = [a1|b_h] @ wf^T + biasy, gated (K=1088 fp8)
    qgemm_k<QEPI_GATE><<<dim3(DI / BN, M_TOK / BM), 256, QSMEM_TOTAL>>>(
        p_yc8, p_wf8, p_biasy, p_f8, nullptr, DI,
        p_gate, nullptr, YK8, INV_Y, S_F);

    // out projection (+ residual), fp32 output
    qgemm_k<QEPI_RESID><<<dim3(D_MODEL / BN, M_TOK / BM), 256, QSMEM_TOTAL>>>(
        p_f8, p_outw8, out_b, d_out, nullptr, D_MODEL,
        nullptr, x, DI, INV_OUT, 0.f);
}